// round 6
// baseline (speedup 1.0000x reference)
#include <cuda_runtime.h>
#include <cuda_fp16.h>
#include <math.h>

// Problem constants
#define BB   16      // batch
#define CI   2048    // input capsules
#define NI   16      // input capsule dim
#define CJ   64      // output capsules
#define NJ   32      // output capsule dim
#define JM   2048    // CJ*NJ
#define K1_CHUNK 2   // i's per prefix chunk (acc reset period)
#define K1_IBLK  4   // i's per K1 block
#define K1_NBLK  (CI / K1_IBLK)           // 512
#define RT_ICHUNK 32                      // i's per routing block (even)
#define RT_NIB    (CI / RT_ICHUNK)        // 64
#define AL2E 11.541560327111707f          // 8 * log2(e)

typedef unsigned long long ull;

// Scratch (allocation-free kernel_launch). g_Uh holds chunk-local PREFIX sums
// of u over i within each 2-i chunk, fp16: even i: P=u_i; odd i: P=u_{i-1}+u_i.
// Layout [i][b][jm].
static __device__ __half g_Uh[(size_t)CI * BB * JM];  // 134 MB
static __device__ float  g_s[BB * JM];                // s accumulator (BSS zero)
static __device__ float  g_v[BB * JM];                // squashed v
static __device__ float  g_bl[(size_t)BB * CI * CJ];  // routing logits [b][i][j]

// ---- packed fp32 pair helpers (fma.rn.f32x2, sm_100+) ----------------------
__device__ __forceinline__ void fma2(ull& d, ull a, ull b) {
    asm("fma.rn.f32x2 %0, %1, %2, %0;" : "+l"(d) : "l"(a), "l"(b));
}
__device__ __forceinline__ ull pack2(float x, float y) {
    ull r; asm("mov.b64 %0, {%1, %2};" : "=l"(r) : "f"(x), "f"(y)); return r;
}
__device__ __forceinline__ float2 unpack2(ull v) {
    float2 r; asm("mov.b64 {%0, %1}, %2;" : "=f"(r.x), "=f"(r.y) : "l"(v)); return r;
}

// ---------------------------------------------------------------------------
// K1: u[b,i,jm] = sum_n x[b,i,n] * w[i,n,jm]; writes 2-i chunk prefix sums as
// fp16. 512 blocks x 512 threads; thread owns jm quad [4t,4t+4).
// v2: X for all 4 i's preloaded once (single sync); flat (i,n-group) pipeline
// with one-group W lookahead so LDGs issue a full group of math early.
// ---------------------------------------------------------------------------
__global__ void __launch_bounds__(512) k_u_prefix(const float* __restrict__ X,
                                                  const float* __restrict__ W)
{
    __shared__ __align__(16) float x_s[K1_IBLK][NI][BB];
    const int t  = threadIdx.x;
    const int i0 = blockIdx.x * K1_IBLK;

    // preload X for all 4 i's (1024 floats), one sync total
#pragma unroll
    for (int rep = 0; rep < 2; rep++) {
        const int idx = t + rep * 512;
        const int ci = idx >> 8, rem = idx & 255, n = rem >> 4, b = rem & 15;
        x_s[ci][n][b] = X[((size_t)b * CI + (i0 + ci)) * NI + n];
    }
    __syncthreads();

    ull acc2[8][4];   // [b-pair][q]: packed (acc[2bp][q], acc[2bp+1][q])

    const float4* W4 = (const float4*)W;
    uint2*        U2 = (uint2*)g_Uh;              // 4 halfs per uint2

    // flat pipeline: 16 (ci, ng) steps, one-group lookahead on W
    float4 cur[4];
#pragma unroll
    for (int k = 0; k < 4; k++)
        cur[k] = W4[(size_t)(i0 * NI + k) * (JM / 4) + t];

#pragma unroll
    for (int g = 0; g < K1_IBLK * 4; g++) {
        const int ci = g >> 2, ng = g & 3;
        const int i  = i0 + ci;

        float4 nxt[4];
        if (g < K1_IBLK * 4 - 1) {
            const int gci = (g + 1) >> 2, gng = (g + 1) & 3;
#pragma unroll
            for (int k = 0; k < 4; k++)
                nxt[k] = W4[(size_t)((i0 + gci) * NI + gng * 4 + k) * (JM / 4) + t];
        }

        if (ng == 0 && (ci & (K1_CHUNK - 1)) == 0) {
#pragma unroll
            for (int bp = 0; bp < 8; bp++)
#pragma unroll
                for (int q = 0; q < 4; q++) acc2[bp][q] = 0ull;
        }

#pragma unroll
        for (int k = 0; k < 4; k++) {
            const int n = ng * 4 + k;
            const ull* xs8 = (const ull*)&x_s[ci][n][0];   // batch pairs
            const float4 wv = cur[k];
            const ull wd0 = pack2(wv.x, wv.x);
            const ull wd1 = pack2(wv.y, wv.y);
            const ull wd2 = pack2(wv.z, wv.z);
            const ull wd3 = pack2(wv.w, wv.w);
#pragma unroll
            for (int bp = 0; bp < 8; bp++) {
                const ull xp = xs8[bp];
                fma2(acc2[bp][0], xp, wd0);
                fma2(acc2[bp][1], xp, wd1);
                fma2(acc2[bp][2], xp, wd2);
                fma2(acc2[bp][3], xp, wd3);
            }
        }

        if (ng == 3) {
            // store fp16 prefix row for this i
#pragma unroll
            for (int bp = 0; bp < 8; bp++) {
                const float2 a0 = unpack2(acc2[bp][0]);
                const float2 a1 = unpack2(acc2[bp][1]);
                const float2 a2 = unpack2(acc2[bp][2]);
                const float2 a3 = unpack2(acc2[bp][3]);
                __half2 lo0 = __floats2half2_rn(a0.x, a1.x);
                __half2 lo1 = __floats2half2_rn(a2.x, a3.x);
                __half2 hi0 = __floats2half2_rn(a0.y, a1.y);
                __half2 hi1 = __floats2half2_rn(a2.y, a3.y);
                uint2 vlo, vhi;
                vlo.x = *(unsigned*)&lo0; vlo.y = *(unsigned*)&lo1;
                vhi.x = *(unsigned*)&hi0; vhi.y = *(unsigned*)&hi1;
                U2[(size_t)(i * BB + 2*bp)     * (JM/4) + t] = vlo;
                U2[(size_t)(i * BB + 2*bp + 1) * (JM/4) + t] = vhi;
            }
        }
#pragma unroll
        for (int k = 0; k < 4; k++) cur[k] = nxt[k];
    }
}

// ---------------------------------------------------------------------------
// K2: s0[b,jm] = sum over odd-i prefix rows (chunk=2). g_s zero beforehand.
// ---------------------------------------------------------------------------
__global__ void __launch_bounds__(256) k_s0_reduce()
{
    const int bid = blockIdx.x;
    const int cq  = bid & 3;
    const int jmc = (bid >> 2) & 7;
    const int b   = bid >> 5;
    const int jm  = jmc * 256 + threadIdx.x;
    const int c0  = cq * (CI / 2 / 4);     // 256 odd rows per quarter

    float a = 0.0f;
#pragma unroll 8
    for (int c = 0; c < CI / 2 / 4; c++) {
        const int i = (c0 + c) * 2 + 1;    // odd i = chunk-last row
        a += __half2float(g_Uh[(size_t)(i * BB + b) * JM + jm]);
    }
    atomicAdd(&g_s[b * JM + jm], a);
}

// ---- fp16 row helpers for routing -----------------------------------------
__device__ __forceinline__ void cvt_row(const uint4& p, float* u) {
    float2 f;
    f = __half22float2(*(__half2*)&p.x); u[0]=f.x; u[1]=f.y;
    f = __half22float2(*(__half2*)&p.y); u[2]=f.x; u[3]=f.y;
    f = __half22float2(*(__half2*)&p.z); u[4]=f.x; u[5]=f.y;
    f = __half22float2(*(__half2*)&p.w); u[6]=f.x; u[7]=f.y;
}

// ---------------------------------------------------------------------------
// Routing pass, 3-phase (pass=1: writes b1; pass=2: reads b1).
// Grid (64, 16) x 256 threads; thread owns jm [8t, 8t+8), j = t>>2.
// Phase A: stream all 32 rows, compute dots -> smem (no barriers).
// Phase B: 1 barrier; warp w computes 64/denominator for i = 4w..4w+3.
// Phase C: 1 barrier; re-stream rows (L2-resident slice), accumulate s.
// ---------------------------------------------------------------------------
__global__ void __launch_bounds__(256) k_route(int pass)
{
    __shared__ float dsm[RT_ICHUNK][CJ];   // 8 KB of logits
    __shared__ float rtot[RT_ICHUNK];      // 64 / sum_j exp

    const int t  = threadIdx.x;
    const int l  = t & 31;
    const int wp = t >> 5;
    const int gl = t & 3;
    const int b  = blockIdx.y;
    const int i0 = blockIdx.x * RT_ICHUNK;
    const int j  = t >> 2;

    float v_r[8];
    {
        const float4* gv4 = (const float4*)g_v;
        float4 va = gv4[b * (JM/4) + 2*t];
        float4 vb = gv4[b * (JM/4) + 2*t + 1];
        v_r[0]=va.x; v_r[1]=va.y; v_r[2]=va.z; v_r[3]=va.w;
        v_r[4]=vb.x; v_r[5]=vb.y; v_r[6]=vb.z; v_r[7]=vb.w;
    }

    const uint4* U4 = (const uint4*)g_Uh;            // 8 halfs per uint4
    const size_t rstride = (size_t)BB * (JM/8);      // uint4 per i step
    const size_t base    = ((size_t)i0 * BB + b) * (JM/8) + t;
    float* BL = g_bl + ((size_t)b * CI + i0) * CJ + j;

    // ---- Phase A: dots ----
#pragma unroll
    for (int bi = 0; bi < RT_ICHUNK / 2; bi++) {
        const uint4 A = U4[base + (size_t)(2*bi)   * rstride];
        const uint4 B = U4[base + (size_t)(2*bi+1) * rstride];
        float uA[8], uB[8];
        cvt_row(A, uA); cvt_row(B, uB);
#pragma unroll
        for (int k = 0; k < 8; k++) uB[k] -= uA[k];

        float dA = 0.0f, dB = 0.0f;
#pragma unroll
        for (int k = 0; k < 8; k++) { dA += v_r[k]*uA[k]; dB += v_r[k]*uB[k]; }
        dA += __shfl_xor_sync(0xffffffffu, dA, 1);
        dA += __shfl_xor_sync(0xffffffffu, dA, 2);
        dB += __shfl_xor_sync(0xffffffffu, dB, 1);
        dB += __shfl_xor_sync(0xffffffffu, dB, 2);

        if (pass == 2) {
            dA += BL[(size_t)(2*bi)     * CJ];
            dB += BL[(size_t)(2*bi + 1) * CJ];
        } else if (gl == 0) {
            BL[(size_t)(2*bi)     * CJ] = dA;
            BL[(size_t)(2*bi + 1) * CJ] = dB;
        }
        if (gl == 0) { dsm[2*bi][j] = dA; dsm[2*bi + 1][j] = dB; }
    }
    __syncthreads();

    // ---- Phase B: softmax denominators (warp-local, no smem reduce) ----
#pragma unroll
    for (int r = 0; r < 4; r++) {
        const int il = wp * 4 + r;
        float e = exp2f(dsm[il][l] * AL2E) + exp2f(dsm[il][l + 32] * AL2E);
#pragma unroll
        for (int o = 16; o > 0; o >>= 1)
            e += __shfl_xor_sync(0xffffffffu, e, o);
        if (l == 0) rtot[il] = __fdividef(64.0f, e);
    }
    __syncthreads();

    // ---- Phase C: weighted accumulation (no shuffles, no barriers) ----
    float s_loc[8];
#pragma unroll
    for (int k = 0; k < 8; k++) s_loc[k] = 0.0f;

#pragma unroll
    for (int bi = 0; bi < RT_ICHUNK / 2; bi++) {
        const uint4 A = U4[base + (size_t)(2*bi)   * rstride];
        const uint4 B = U4[base + (size_t)(2*bi+1) * rstride];
        float uA[8], uB[8];
        cvt_row(A, uA); cvt_row(B, uB);
#pragma unroll
        for (int k = 0; k < 8; k++) uB[k] -= uA[k];

        const float ccA = exp2f(dsm[2*bi][j]     * AL2E) * rtot[2*bi];
        const float ccB = exp2f(dsm[2*bi + 1][j] * AL2E) * rtot[2*bi + 1];
#pragma unroll
        for (int k = 0; k < 8; k++) s_loc[k] += ccA * uA[k] + ccB * uB[k];
    }

#pragma unroll
    for (int k = 0; k < 8; k++)
        atomicAdd(&g_s[b * JM + 8*t + k], s_loc[k]);
}

// ---------------------------------------------------------------------------
// Squash: v = (|s|^2/(1+|s|^2)) * s * rsqrt(|s|^2 + eps). Re-zeroes g_s.
// ---------------------------------------------------------------------------
__global__ void __launch_bounds__(512) k_squash(float* dst)
{
    const int t    = threadIdx.x;
    const int gw   = blockIdx.x * 16 + (t >> 5);
    const int lane = t & 31;
    const int b    = gw >> 6;
    const int j    = gw & 63;
    const int idx  = b * JM + j * NJ + lane;

    const float s = g_s[idx];
    float sq = s * s;
#pragma unroll
    for (int o = 16; o > 0; o >>= 1)
        sq += __shfl_xor_sync(0xffffffffu, sq, o);

    const float coef = (sq / (1.0f + sq)) * rsqrtf(sq + 1e-7f);
    float* out = dst ? dst : g_v;
    out[idx] = s * coef;
    g_s[idx] = 0.0f;
}

// ---------------------------------------------------------------------------
extern "C" void kernel_launch(void* const* d_in, const int* in_sizes, int n_in,
                              void* d_out, int out_size)
{
    const float* X = (const float*)d_in[0];
    const float* W = (const float*)d_in[1];
    if (n_in >= 2 && in_sizes[0] > in_sizes[1]) {   // defensive order check
        const float* tmp = X; X = W; W = tmp;
    }
    float* out = (float*)d_out;

    k_u_prefix<<<K1_NBLK, 512>>>(X, W);
    k_s0_reduce<<<512, 256>>>();
    k_squash<<<64, 512>>>(nullptr);                 // v0, zero g_s
    k_route<<<dim3(RT_NIB, BB), 256>>>(1);
    k_squash<<<64, 512>>>(nullptr);                 // v1, zero g_s
    k_route<<<dim3(RT_NIB, BB), 256>>>(2);
    k_squash<<<64, 512>>>(out);                     // v2 -> output, zero g_s
    (void)out_size;
}